// round 1
// baseline (speedup 1.0000x reference)
#include <cuda_runtime.h>
#include <cuda_bf16.h>
#include <math.h>

// ---------------------------------------------------------------------------
// Problem constants
// ---------------------------------------------------------------------------
#define T_SEQ    2048
#define D_MODEL  2048
#define N_HEADS  32
#define N_KV     8
#define HEAD_DIM 64
#define KV_DIM   (N_KV * HEAD_DIM)     // 512
#define WINDOW_HALF 256                // rows keep cols [i-256, i+256)

// ---------------------------------------------------------------------------
// Scratch (device globals; no allocation allowed)
// ---------------------------------------------------------------------------
__device__ float g_Q[(size_t)T_SEQ * D_MODEL];     // 16 MB
__device__ float g_K[(size_t)T_SEQ * KV_DIM];      // 4 MB
__device__ float g_V[(size_t)T_SEQ * KV_DIM];      // 4 MB
__device__ float g_O[(size_t)T_SEQ * D_MODEL];     // 16 MB
__device__ float g_cos[T_SEQ * 32];
__device__ float g_sin[T_SEQ * 32];

// ---------------------------------------------------------------------------
// Tiled fp32 GEMM:  C[M,N] = A[M,K] * B[N,K]^T   (both row-major, K-contig)
// BM=BN=128, BK=16, 256 threads, 8x8 per thread.
// Assumes M%128==0, N%128==0, K%16==0 (true for all our shapes).
// ---------------------------------------------------------------------------
#define BM 128
#define BN 128
#define BK 16
#define SPAD 132   // padded smem row stride (multiple of 4 for float4)

__global__ void __launch_bounds__(256, 2)
gemm_nt(const float* __restrict__ A, const float* __restrict__ B,
        float* __restrict__ C, int M, int N, int K)
{
    __shared__ float As[BK][SPAD];
    __shared__ float Bs[BK][SPAD];

    const int tid = threadIdx.x;
    const int bm = blockIdx.y * BM;
    const int bn = blockIdx.x * BN;

    const int tr = tid / 16;        // 0..15  -> rows tr*8 .. tr*8+7
    const int tc = tid % 16;        // 0..15  -> cols tc*8 .. tc*8+7

    const int loadRow  = tid / 4;         // 0..63
    const int loadCol  = (tid % 4) * 4;   // 0,4,8,12

    float acc[8][8];
#pragma unroll
    for (int i = 0; i < 8; i++)
#pragma unroll
        for (int j = 0; j < 8; j++) acc[i][j] = 0.f;

    for (int k0 = 0; k0 < K; k0 += BK) {
        // stage A and B tiles (transposed to K-major in smem)
#pragma unroll
        for (int it = 0; it < 2; it++) {
            const int r = loadRow + it * 64;
            float4 va = *(const float4*)(A + (size_t)(bm + r) * K + k0 + loadCol);
            As[loadCol + 0][r] = va.x;
            As[loadCol + 1][r] = va.y;
            As[loadCol + 2][r] = va.z;
            As[loadCol + 3][r] = va.w;
            float4 vb = *(const float4*)(B + (size_t)(bn + r) * K + k0 + loadCol);
            Bs[loadCol + 0][r] = vb.x;
            Bs[loadCol + 1][r] = vb.y;
            Bs[loadCol + 2][r] = vb.z;
            Bs[loadCol + 3][r] = vb.w;
        }
        __syncthreads();

#pragma unroll
        for (int kk = 0; kk < BK; kk++) {
            float4 a0 = *(const float4*)&As[kk][tr * 8];
            float4 a1 = *(const float4*)&As[kk][tr * 8 + 4];
            float4 b0 = *(const float4*)&Bs[kk][tc * 8];
            float4 b1 = *(const float4*)&Bs[kk][tc * 8 + 4];
            float a[8] = {a0.x, a0.y, a0.z, a0.w, a1.x, a1.y, a1.z, a1.w};
            float b[8] = {b0.x, b0.y, b0.z, b0.w, b1.x, b1.y, b1.z, b1.w};
#pragma unroll
            for (int i = 0; i < 8; i++)
#pragma unroll
                for (int j = 0; j < 8; j++)
                    acc[i][j] = fmaf(a[i], b[j], acc[i][j]);
        }
        __syncthreads();
    }

#pragma unroll
    for (int i = 0; i < 8; i++) {
        const size_t row = (size_t)(bm + tr * 8 + i);
        float4 v0 = make_float4(acc[i][0], acc[i][1], acc[i][2], acc[i][3]);
        float4 v1 = make_float4(acc[i][4], acc[i][5], acc[i][6], acc[i][7]);
        *(float4*)(C + row * N + bn + tc * 8)     = v0;
        *(float4*)(C + row * N + bn + tc * 8 + 4) = v1;
    }
}

// ---------------------------------------------------------------------------
// RoPE tables: cos/sin(t * 10000^{-i/32}) with double-precision angle
// reduction (safe under fast-math; args up to 2048 rad otherwise).
// ---------------------------------------------------------------------------
__global__ void rope_tables()
{
    int idx = blockIdx.x * blockDim.x + threadIdx.x;   // 0 .. T*32-1
    if (idx >= T_SEQ * 32) return;
    int i = idx & 31;
    int t = idx >> 5;
    // inv_freq = 10000^{-(2i)/64} = 2^{-(i/32)*log2(10000)}
    double invf = exp2(-(double)i / 32.0 * 13.287712379549449392);
    double ang  = fmod((double)t * invf, 6.28318530717958647692);
    g_cos[idx] = cosf((float)ang);
    g_sin[idx] = sinf((float)ang);
}

__global__ void rope_apply(float* __restrict__ X, int nheads)
{
    int idx = blockIdx.x * blockDim.x + threadIdx.x;
    int total = T_SEQ * nheads * 32;
    if (idx >= total) return;
    int i = idx & 31;
    int h = (idx >> 5) % nheads;
    int t = idx / (32 * nheads);
    float c = g_cos[t * 32 + i];
    float s = g_sin[t * 32 + i];
    float* row = X + (size_t)t * (nheads * HEAD_DIM) + h * HEAD_DIM;
    float x0 = row[i];
    float x1 = row[i + 32];
    row[i]      = x0 * c - x1 * s;
    row[i + 32] = x1 * c + x0 * s;
}

// ---------------------------------------------------------------------------
// Banded GQA attention. One warp per query row; 16 queries (one head) per
// block. K/V streamed through smem in chunks of 64 keys. Scores are bounded
// (|s| < ~8) so softmax needs no max subtraction.
// ---------------------------------------------------------------------------
#define TQ 16      // queries per block (= warps per block)
#define CH 64      // kv chunk

__global__ void __launch_bounds__(TQ * 32)
attn_kernel(const float* __restrict__ Q, const float* __restrict__ K,
            const float* __restrict__ V, float* __restrict__ O)
{
    __shared__ float Kst[CH][CH + 1];  // transposed: [d][j], padded
    __shared__ float Vs[CH][CH];       // [j][d]

    const int h  = blockIdx.y;
    const int g  = h >> 2;                 // kv head
    const int i0 = blockIdx.x * TQ;
    const int w  = threadIdx.x >> 5;
    const int l  = threadIdx.x & 31;
    const int i  = i0 + w;                 // this warp's query row

    const float q0 = Q[(size_t)i * D_MODEL + h * HEAD_DIM + l];
    const float q1 = Q[(size_t)i * D_MODEL + h * HEAD_DIM + 32 + l];

    float o0 = 0.f, o1 = 0.f, ssum = 0.f;

    const int jlo = max(0, i - WINDOW_HALF);
    const int jhi = min(T_SEQ, i + WINDOW_HALF);

    const int jstart = max(0, i0 - WINDOW_HALF);
    const int jend   = min(T_SEQ, i0 + TQ - 1 + WINDOW_HALF);

    for (int c = jstart; c < jend; c += CH) {
        __syncthreads();
        // cooperative load: 64x64 K (transposed) + 64x64 V, 512 thr x 2 float4
#pragma unroll
        for (int it = 0; it < 2; it++) {
            int idx = threadIdx.x + it * (TQ * 32);   // 0..1023
            int j  = idx >> 4;
            int d4 = (idx & 15) * 4;
            int ja = c + j;
            float4 kv, vv;
            if (ja < T_SEQ) {
                kv = *(const float4*)(K + (size_t)ja * KV_DIM + g * HEAD_DIM + d4);
                vv = *(const float4*)(V + (size_t)ja * KV_DIM + g * HEAD_DIM + d4);
            } else {
                kv = make_float4(0.f, 0.f, 0.f, 0.f);
                vv = kv;
            }
            Kst[d4 + 0][j] = kv.x;
            Kst[d4 + 1][j] = kv.y;
            Kst[d4 + 2][j] = kv.z;
            Kst[d4 + 3][j] = kv.w;
            *(float4*)&Vs[j][d4] = vv;
        }
        __syncthreads();

        // scores: lane l owns keys (c+l) and (c+l+32)
        float s0 = 0.f, s1 = 0.f;
#pragma unroll
        for (int d = 0; d < 32; d++) {
            float qa = __shfl_sync(0xffffffffu, q0, d);
            s0 = fmaf(qa, Kst[d][l],      s0);
            s1 = fmaf(qa, Kst[d][l + 32], s1);
        }
#pragma unroll
        for (int d = 0; d < 32; d++) {
            float qa = __shfl_sync(0xffffffffu, q1, d);
            s0 = fmaf(qa, Kst[32 + d][l],      s0);
            s1 = fmaf(qa, Kst[32 + d][l + 32], s1);
        }
        const int ja0 = c + l, ja1 = c + l + 32;
        float p0 = (ja0 >= jlo && ja0 < jhi) ? __expf(s0 * 0.125f) : 0.f;
        float p1 = (ja1 >= jlo && ja1 < jhi) ? __expf(s1 * 0.125f) : 0.f;
        ssum += p0 + p1;

        // PV: broadcast p_j, accumulate o over d (lane l holds d=l, d=l+32)
#pragma unroll
        for (int j = 0; j < 32; j++) {
            float pa = __shfl_sync(0xffffffffu, p0, j);
            o0 = fmaf(pa, Vs[j][l],      o0);
            o1 = fmaf(pa, Vs[j][l + 32], o1);
            float pb = __shfl_sync(0xffffffffu, p1, j);
            o0 = fmaf(pb, Vs[j + 32][l],      o0);
            o1 = fmaf(pb, Vs[j + 32][l + 32], o1);
        }
    }

    // total softmax denominator (p's were lane-partitioned)
#pragma unroll
    for (int off = 16; off; off >>= 1)
        ssum += __shfl_xor_sync(0xffffffffu, ssum, off);
    const float inv = 1.f / ssum;

    O[(size_t)i * D_MODEL + h * HEAD_DIM + l]      = o0 * inv;
    O[(size_t)i * D_MODEL + h * HEAD_DIM + 32 + l] = o1 * inv;
}

// ---------------------------------------------------------------------------
// Launch
// ---------------------------------------------------------------------------
extern "C" void kernel_launch(void* const* d_in, const int* in_sizes, int n_in,
                              void* d_out, int out_size)
{
    const float* X  = (const float*)d_in[0];
    const float* Wq = (const float*)d_in[1];
    const float* Wk = (const float*)d_in[2];
    const float* Wv = (const float*)d_in[3];
    const float* Wo = (const float*)d_in[4];
    float* out = (float*)d_out;

    float* Qb;  cudaGetSymbolAddress((void**)&Qb, g_Q);
    float* Kb;  cudaGetSymbolAddress((void**)&Kb, g_K);
    float* Vb;  cudaGetSymbolAddress((void**)&Vb, g_V);
    float* Ob;  cudaGetSymbolAddress((void**)&Ob, g_O);

    // RoPE tables (independent of GEMMs)
    rope_tables<<<(T_SEQ * 32 + 255) / 256, 256>>>();

    // projections
    gemm_nt<<<dim3(D_MODEL / BN, T_SEQ / BM), 256>>>(X, Wq, Qb, T_SEQ, D_MODEL, D_MODEL);
    gemm_nt<<<dim3(KV_DIM  / BN, T_SEQ / BM), 256>>>(X, Wk, Kb, T_SEQ, KV_DIM,  D_MODEL);
    gemm_nt<<<dim3(KV_DIM  / BN, T_SEQ / BM), 256>>>(X, Wv, Vb, T_SEQ, KV_DIM,  D_MODEL);

    // RoPE on Q and K
    rope_apply<<<(T_SEQ * N_HEADS * 32 + 255) / 256, 256>>>(Qb, N_HEADS);
    rope_apply<<<(T_SEQ * N_KV    * 32 + 255) / 256, 256>>>(Kb, N_KV);

    // banded attention
    attn_kernel<<<dim3(T_SEQ / TQ, N_HEADS), TQ * 32>>>(Qb, Kb, Vb, Ob);

    // output projection
    gemm_nt<<<dim3(D_MODEL / BN, T_SEQ / BM), 256>>>(Ob, Wo, out, T_SEQ, D_MODEL, D_MODEL);
}